// round 11
// baseline (speedup 1.0000x reference)
#include <cuda_runtime.h>
#include <cuda_fp16.h>
#include <cstdint>

#define K_DIM   4096
#define N_DIM   11008
#define BM      128
#define BN      128
#define BK      32
#define THREADS 256
#define ASTR    40            // padded row stride (halfs): 80B rows -> conflict-free ldmatrix
#define KTILES  (K_DIM / BK)  // 128
#define NGROUPS (K_DIM / 128) // 32 scale groups

// smem layout (bytes):
//   As32 : [2][BM][BK] float  = 32768
//   As16 : [BM][ASTR]  half   = 10240
//   Bs   : [BN][ASTR]  half   = 10240
//   Ps   : [2][BK/8][BN] int  =  4096
//   Ss   : [NGROUPS][BN] half =  8192
//   total                      = 65536
#define SMEM_BYTES 65536

static __device__ __forceinline__ unsigned smem_u32(const void* p) {
    return (unsigned)__cvta_generic_to_shared(p);
}

static __device__ __forceinline__ void cp_async16(unsigned dst, const void* src) {
    asm volatile("cp.async.cg.shared.global [%0], [%1], 16;\n" :: "r"(dst), "l"(src));
}

__global__ void __launch_bounds__(THREADS, 2)
quantlinear_kernel(const float* __restrict__ x,
                   const int*   __restrict__ packed,
                   const float* __restrict__ scales,
                   const float* __restrict__ bias,
                   float*       __restrict__ out,
                   int M)
{
    extern __shared__ char smem[];
    float*  As32 = reinterpret_cast<float*>(smem);                 // [2][BM][BK]
    __half* As16 = reinterpret_cast<__half*>(As32 + 2 * BM * BK);  // [BM][ASTR]
    __half* Bs   = As16 + BM * ASTR;                               // [BN][ASTR]
    int*    Ps   = reinterpret_cast<int*>(Bs + BN * ASTR);         // [2][4][BN]
    __half* Ss   = reinterpret_cast<__half*>(Ps + 2 * 4 * BN);     // [NGROUPS][BN]

    const int tid    = threadIdx.x;
    const int lane   = tid & 31;
    const int wid    = tid >> 5;
    const int warp_m = wid >> 1;   // 0..3  -> 32 rows each
    const int warp_n = wid & 1;    // 0..1  -> 64 cols each
    const int m0 = blockIdx.y * BM;
    const int n0 = blockIdx.x * BN;

    // ---- preload all scale groups for this N-slab (fp32 in gmem -> half in smem) ----
    for (int i = tid; i < NGROUPS * BN; i += THREADS) {
        int g = i >> 7, n = i & 127;
        Ss[i] = __float2half(scales[(size_t)g * N_DIM + n0 + n]);
    }

    float acc[2][8][4];
    #pragma unroll
    for (int mi = 0; mi < 2; mi++)
        #pragma unroll
        for (int ni = 0; ni < 8; ni++)
            #pragma unroll
            for (int j = 0; j < 4; j++) acc[mi][ni][j] = 0.f;

    // ---- issue K-tile 0 into buffer 0 ----
    {
        #pragma unroll
        for (int i = 0; i < 4; i++) {                // A: 128x32 fp32 = 1024 float4
            int c = i * THREADS + tid;
            int m = c >> 3, kc = c & 7;
            cp_async16(smem_u32(As32 + m * BK + kc * 4),
                       x + (size_t)(m0 + m) * K_DIM + kc * 4);
        }
        if (tid < 128) {                             // P: 4x128 int = 128 x 16B
            int w0 = tid * 4;
            int kw = w0 >> 7, n = w0 & 127;
            cp_async16(smem_u32(Ps + w0),
                       packed + (size_t)kw * N_DIM + n0 + n);
        }
        asm volatile("cp.async.commit_group;\n" ::: "memory");
    }

    const __half2 h1032 = __half2half2(__ushort_as_half(0x6408));  // 1024 + 8

    for (int t = 0; t < KTILES; t++) {
        const int cur = t & 1;

        asm volatile("cp.async.wait_group 0;\n" ::: "memory");
        __syncthreads();   // tile t landed; As16/Bs free (mma of t-1 done)

        // ---- prefetch tile t+1 into the other buffer ----
        if (t + 1 < KTILES) {
            const int kt = (t + 1) * BK;
            const int nb = cur ^ 1;
            #pragma unroll
            for (int i = 0; i < 4; i++) {
                int c = i * THREADS + tid;
                int m = c >> 3, kc = c & 7;
                cp_async16(smem_u32(As32 + nb * BM * BK + m * BK + kc * 4),
                           x + (size_t)(m0 + m) * K_DIM + kt + kc * 4);
            }
            if (tid < 128) {
                int w0 = tid * 4;
                int kw = w0 >> 7, n = w0 & 127;
                cp_async16(smem_u32(Ps + nb * 4 * BN + w0),
                           packed + (size_t)(kt / 8 + kw) * N_DIM + n0 + n);
            }
            asm volatile("cp.async.commit_group;\n" ::: "memory");
        }

        // ---- dequant packed tile -> Bs [n][k] fp16 ----
        // NOTE: subtract the 1032 magic EXACTLY in fp16 first (q-8 is a small
        // integer, exact), THEN multiply by scale (one rounding). Fusing the
        // offset into an hfma pre-rounds 1032*s and cancels catastrophically.
        {
            const int g = t >> 2;  // 32-wide tile -> 128-wide scale group
            #pragma unroll
            for (int i = 0; i < 2; i++) {
                int c = i * THREADS + tid;
                int n = c & 127, kw = c >> 7;
                int w = Ps[cur * 4 * BN + kw * BN + n];
                __half2 s2 = __half2half2(Ss[g * BN + n]);
                uint4 ov;
                unsigned* op = reinterpret_cast<unsigned*>(&ov);
                #pragma unroll
                for (int j = 0; j < 4; j++) {
                    unsigned tt = ((unsigned)w) >> (8 * j);
                    unsigned bits = (tt & 0xFu) | ((tt & 0xF0u) << 12) | 0x64006400u;
                    __half2 h2 = *reinterpret_cast<__half2*>(&bits); // {1024+qlo, 1024+qhi}
                    __half2 r  = __hmul2(__hsub2(h2, h1032), s2);    // exact (q-8), then *s
                    op[j] = *reinterpret_cast<unsigned*>(&r);
                }
                *reinterpret_cast<uint4*>(Bs + n * ASTR + kw * 8) = ov;
            }
        }

        // ---- convert A tile fp32 -> fp16 (smem -> smem) ----
        {
            const float* Ab = As32 + cur * BM * BK;
            #pragma unroll
            for (int i = 0; i < 4; i++) {
                int c = i * THREADS + tid;
                int m = c >> 3, kc = c & 7;
                float4 v = *reinterpret_cast<const float4*>(Ab + m * BK + kc * 4);
                __half2 h0 = __floats2half2_rn(v.x, v.y);
                __half2 h1 = __floats2half2_rn(v.z, v.w);
                uint2 pr;
                pr.x = *reinterpret_cast<unsigned*>(&h0);
                pr.y = *reinterpret_cast<unsigned*>(&h1);
                *reinterpret_cast<uint2*>(As16 + m * ASTR + kc * 4) = pr;
            }
        }
        __syncthreads();   // dequant + convert visible

        // ---- mma over the 128x128x32 tile ----
        {
            const int a_row = warp_m * 32 + (lane & 7) + ((lane >> 3) & 1) * 8;
            const int a_col = ((lane >> 4) & 1) * 8;
            const int b_row = warp_n * 64 + (lane & 7) + ((lane >> 4) & 1) * 8;
            const int b_col = ((lane >> 3) & 1) * 8;

            #pragma unroll
            for (int kk = 0; kk < 2; kk++) {
                unsigned a[2][4];
                #pragma unroll
                for (int mi = 0; mi < 2; mi++) {
                    unsigned addr = smem_u32(As16 + (a_row + mi * 16) * ASTR + kk * 16 + a_col);
                    asm volatile("ldmatrix.sync.aligned.m8n8.x4.shared.b16 {%0,%1,%2,%3}, [%4];\n"
                                 : "=r"(a[mi][0]), "=r"(a[mi][1]), "=r"(a[mi][2]), "=r"(a[mi][3])
                                 : "r"(addr));
                }
                unsigned b[8][2];
                #pragma unroll
                for (int ni4 = 0; ni4 < 4; ni4++) {
                    unsigned addr = smem_u32(Bs + (b_row + ni4 * 16) * ASTR + kk * 16 + b_col);
                    asm volatile("ldmatrix.sync.aligned.m8n8.x4.shared.b16 {%0,%1,%2,%3}, [%4];\n"
                                 : "=r"(b[2*ni4][0]), "=r"(b[2*ni4][1]),
                                   "=r"(b[2*ni4+1][0]), "=r"(b[2*ni4+1][1])
                                 : "r"(addr));
                }
                #pragma unroll
                for (int mi = 0; mi < 2; mi++)
                    #pragma unroll
                    for (int ni = 0; ni < 8; ni++) {
                        asm volatile(
                            "mma.sync.aligned.m16n8k16.row.col.f32.f16.f16.f32 "
                            "{%0,%1,%2,%3}, {%4,%5,%6,%7}, {%8,%9}, {%0,%1,%2,%3};\n"
                            : "+f"(acc[mi][ni][0]), "+f"(acc[mi][ni][1]),
                              "+f"(acc[mi][ni][2]), "+f"(acc[mi][ni][3])
                            : "r"(a[mi][0]), "r"(a[mi][1]), "r"(a[mi][2]), "r"(a[mi][3]),
                              "r"(b[ni][0]), "r"(b[ni][1]));
                    }
            }
        }
    }

    // ---- epilogue: add bias (fp32), store fp32 ----
    #pragma unroll
    for (int mi = 0; mi < 2; mi++) {
        #pragma unroll
        for (int ni = 0; ni < 8; ni++) {
            int r = m0 + warp_m * 32 + mi * 16 + (lane >> 2);
            int c = n0 + warp_n * 64 + ni * 8 + 2 * (lane & 3);
            float2 bb = *reinterpret_cast<const float2*>(bias + c);
            float2 v0 = make_float2(acc[mi][ni][0] + bb.x, acc[mi][ni][1] + bb.y);
            float2 v1 = make_float2(acc[mi][ni][2] + bb.x, acc[mi][ni][3] + bb.y);
            *reinterpret_cast<float2*>(out + (size_t)r * N_DIM + c) = v0;
            *reinterpret_cast<float2*>(out + (size_t)(r + 8) * N_DIM + c) = v1;
        }
    }
}

extern "C" void kernel_launch(void* const* d_in, const int* in_sizes, int n_in,
                              void* d_out, int out_size) {
    const float* x      = (const float*)d_in[0];
    const int*   packed = (const int*)d_in[1];
    const float* scales = (const float*)d_in[2];
    const float* bias   = (const float*)d_in[3];
    float*       out    = (float*)d_out;

    const int M = in_sizes[0] / K_DIM;   // 4*1024 = 4096 (element count, dtype-independent)

    cudaFuncSetAttribute(quantlinear_kernel,
                         cudaFuncAttributeMaxDynamicSharedMemorySize, SMEM_BYTES);

    dim3 grid(N_DIM / BN, M / BM);       // (86, 32)
    quantlinear_kernel<<<grid, THREADS, SMEM_BYTES>>>(x, packed, scales, bias, out, M);
}

// round 13
// speedup vs baseline: 1.3844x; 1.3844x over previous
#include <cuda_runtime.h>
#include <cuda_fp16.h>
#include <cstdint>

#define K_DIM   4096
#define N_DIM   11008
#define BM      128
#define BN      128
#define BK      64
#define THREADS 256
#define ASTR    72              // padded row stride (halfs): 144B rows, conflict-free ldmatrix
#define KTILES  (K_DIM / BK)    // 64
#define NGROUPS (K_DIM / 128)   // 32

// smem layout (halfs/ints):
//   As16 : [2][BM][ASTR] half = 36864 B
//   Bs   : [2][BN][ASTR] half = 36864 B
//   Ps   : [2][8][BN]    int  =  8192 B
//   Ss   : [NGROUPS][BN] half =  8192 B
#define SMEM_BYTES 90112
#define ABUF (BM * ASTR)        // halfs per A/B buffer

// fp16 copy of x, produced once by convert_kernel (scratch via __device__ global)
__device__ __half x16g[(size_t)4096 * (size_t)K_DIM];

static __device__ __forceinline__ unsigned smem_u32(const void* p) {
    return (unsigned)__cvta_generic_to_shared(p);
}
static __device__ __forceinline__ void cp_async16(unsigned dst, const void* src) {
    asm volatile("cp.async.cg.shared.global [%0], [%1], 16;\n" :: "r"(dst), "l"(src));
}

__global__ void __launch_bounds__(256)
convert_kernel(const float* __restrict__ x) {
    size_t i = ((size_t)blockIdx.x * 256 + threadIdx.x) * 4;
    float4 v = *reinterpret_cast<const float4*>(x + i);
    __half2 h0 = __floats2half2_rn(v.x, v.y);
    __half2 h1 = __floats2half2_rn(v.z, v.w);
    uint2 p;
    p.x = *reinterpret_cast<unsigned*>(&h0);
    p.y = *reinterpret_cast<unsigned*>(&h1);
    *reinterpret_cast<uint2*>(x16g + i) = p;
}

__global__ void __launch_bounds__(THREADS, 2)
quantlinear_kernel(const int*   __restrict__ packed,
                   const float* __restrict__ scales,
                   const float* __restrict__ bias,
                   float*       __restrict__ out)
{
    extern __shared__ char smem[];
    __half* As16 = reinterpret_cast<__half*>(smem);               // [2][BM][ASTR]
    __half* Bs   = As16 + 2 * ABUF;                               // [2][BN][ASTR]
    int*    Ps   = reinterpret_cast<int*>(Bs + 2 * ABUF);         // [2][8][BN]
    __half* Ss   = reinterpret_cast<__half*>(Ps + 2 * 8 * BN);    // [NGROUPS][BN]

    const int tid    = threadIdx.x;
    const int lane   = tid & 31;
    const int wid    = tid >> 5;
    const int warp_m = wid >> 1;   // 0..3 -> 32 rows each
    const int warp_n = wid & 1;    // 0..1 -> 64 cols each
    const int m0 = blockIdx.y * BM;
    const int n0 = blockIdx.x * BN;

    // ---- preload scale groups for this N-slab ----
    for (int i = tid; i < NGROUPS * BN; i += THREADS) {
        int g = i >> 7, n = i & 127;
        Ss[i] = __float2half(scales[(size_t)g * N_DIM + n0 + n]);
    }

    float acc[2][8][4];
    #pragma unroll
    for (int mi = 0; mi < 2; mi++)
        #pragma unroll
        for (int ni = 0; ni < 8; ni++)
            #pragma unroll
            for (int j = 0; j < 4; j++) acc[mi][ni][j] = 0.f;

    // ---- issue tile 0 (A fp16 + packed) into buffer 0 ----
    {
        #pragma unroll
        for (int i = 0; i < 4; i++) {                 // A: 128x64 half = 1024 x 16B
            int c = i * THREADS + tid;
            int m = c >> 3, kc = c & 7;
            cp_async16(smem_u32(As16 + m * ASTR + kc * 8),
                       x16g + (size_t)(m0 + m) * K_DIM + kc * 8);
        }
        {                                             // P: 8x128 int = 256 x 16B
            int kw = tid >> 5, n4 = (tid & 31) * 4;
            cp_async16(smem_u32(Ps + kw * 128 + n4),
                       packed + (size_t)kw * N_DIM + n0 + n4);
        }
        asm volatile("cp.async.commit_group;\n" ::: "memory");
    }

    const int dq_n = tid & 127;
    const __half2 h1032 = __half2half2(__ushort_as_half(0x6408));  // 1024 + 8

    for (int t = 0; t < KTILES; t++) {
        const int cur = t & 1;

        asm volatile("cp.async.wait_group 0;\n" ::: "memory");
        __syncthreads();   // A(t), P(t) visible to all; all mma(t-1) complete

        // ---- dequant packed tile -> Bs[cur] (exact (q-8), then *s) ----
        {
            const int g = t >> 1;
            const int* Pb = Ps + cur * 8 * BN;
            __half* Bb = Bs + cur * ABUF;
            const __half2 s2 = __half2half2(Ss[g * BN + dq_n]);
            #pragma unroll
            for (int i = 0; i < 4; i++) {
                const int kw = 2 * i + (tid >> 7);
                int w = Pb[kw * BN + dq_n];
                uint4 ov;
                unsigned* op = reinterpret_cast<unsigned*>(&ov);
                #pragma unroll
                for (int j = 0; j < 4; j++) {
                    unsigned tt = ((unsigned)w) >> (8 * j);
                    unsigned bits = (tt & 0xFu) | ((tt & 0xF0u) << 12) | 0x64006400u;
                    __half2 h2 = *reinterpret_cast<__half2*>(&bits);
                    __half2 r  = __hmul2(__hsub2(h2, h1032), s2);
                    op[j] = *reinterpret_cast<unsigned*>(&r);
                }
                *reinterpret_cast<uint4*>(Bb + dq_n * ASTR + kw * 8) = ov;
            }
        }

        // ---- prefetch tile t+1 into the other buffers (safe: past sync) ----
        if (t + 1 < KTILES) {
            const int nb = cur ^ 1;
            const size_t kt = (size_t)(t + 1) * BK;
            #pragma unroll
            for (int i = 0; i < 4; i++) {
                int c = i * THREADS + tid;
                int m = c >> 3, kc = c & 7;
                cp_async16(smem_u32(As16 + nb * ABUF + m * ASTR + kc * 8),
                           x16g + (size_t)(m0 + m) * K_DIM + kt + kc * 8);
            }
            {
                int kw = tid >> 5, n4 = (tid & 31) * 4;
                cp_async16(smem_u32(Ps + nb * 8 * BN + kw * 128 + n4),
                           packed + (size_t)((t + 1) * 8 + kw) * N_DIM + n0 + n4);
            }
            asm volatile("cp.async.commit_group;\n" ::: "memory");
        }
        __syncthreads();   // Bs[cur] visible

        // ---- mma over the 128x128x64 tile ----
        {
            const __half* Ab = As16 + cur * ABUF;
            const __half* Bb = Bs + cur * ABUF;
            const int a_row = warp_m * 32 + (lane & 7) + ((lane >> 3) & 1) * 8;
            const int a_col = ((lane >> 4) & 1) * 8;
            const int b_row = warp_n * 64 + (lane & 7) + ((lane >> 4) & 1) * 8;
            const int b_col = ((lane >> 3) & 1) * 8;

            #pragma unroll
            for (int kk = 0; kk < 4; kk++) {
                unsigned a[2][4];
                #pragma unroll
                for (int mi = 0; mi < 2; mi++) {
                    unsigned addr = smem_u32(Ab + (a_row + mi * 16) * ASTR + kk * 16 + a_col);
                    asm volatile("ldmatrix.sync.aligned.m8n8.x4.shared.b16 {%0,%1,%2,%3}, [%4];\n"
                                 : "=r"(a[mi][0]), "=r"(a[mi][1]), "=r"(a[mi][2]), "=r"(a[mi][3])
                                 : "r"(addr));
                }
                unsigned b[8][2];
                #pragma unroll
                for (int ni4 = 0; ni4 < 4; ni4++) {
                    unsigned addr = smem_u32(Bb + (b_row + ni4 * 16) * ASTR + kk * 16 + b_col);
                    asm volatile("ldmatrix.sync.aligned.m8n8.x4.shared.b16 {%0,%1,%2,%3}, [%4];\n"
                                 : "=r"(b[2*ni4][0]), "=r"(b[2*ni4][1]),
                                   "=r"(b[2*ni4+1][0]), "=r"(b[2*ni4+1][1])
                                 : "r"(addr));
                }
                #pragma unroll
                for (int mi = 0; mi < 2; mi++)
                    #pragma unroll
                    for (int ni = 0; ni < 8; ni++) {
                        asm volatile(
                            "mma.sync.aligned.m16n8k16.row.col.f32.f16.f16.f32 "
                            "{%0,%1,%2,%3}, {%4,%5,%6,%7}, {%8,%9}, {%0,%1,%2,%3};\n"
                            : "+f"(acc[mi][ni][0]), "+f"(acc[mi][ni][1]),
                              "+f"(acc[mi][ni][2]), "+f"(acc[mi][ni][3])
                            : "r"(a[mi][0]), "r"(a[mi][1]), "r"(a[mi][2]), "r"(a[mi][3]),
                              "r"(b[ni][0]), "r"(b[ni][1]));
                    }
            }
        }
    }

    // ---- epilogue: add bias (fp32), store fp32 ----
    #pragma unroll
    for (int mi = 0; mi < 2; mi++) {
        #pragma unroll
        for (int ni = 0; ni < 8; ni++) {
            int r = m0 + warp_m * 32 + mi * 16 + (lane >> 2);
            int c = n0 + warp_n * 64 + ni * 8 + 2 * (lane & 3);
            float2 bb = *reinterpret_cast<const float2*>(bias + c);
            float2 v0 = make_float2(acc[mi][ni][0] + bb.x, acc[mi][ni][1] + bb.y);
            float2 v1 = make_float2(acc[mi][ni][2] + bb.x, acc[mi][ni][3] + bb.y);
            *reinterpret_cast<float2*>(out + (size_t)r * N_DIM + c) = v0;
            *reinterpret_cast<float2*>(out + (size_t)(r + 8) * N_DIM + c) = v1;
        }
    }
}

extern "C" void kernel_launch(void* const* d_in, const int* in_sizes, int n_in,
                              void* d_out, int out_size) {
    const float* x      = (const float*)d_in[0];
    const int*   packed = (const int*)d_in[1];
    const float* scales = (const float*)d_in[2];
    const float* bias   = (const float*)d_in[3];
    float*       out    = (float*)d_out;

    const int M = in_sizes[0] / K_DIM;   // 4096

    // 1) x fp32 -> fp16 scratch (one-time per launch, ~20us)
    {
        int n = M * K_DIM;               // 16.78M elements
        convert_kernel<<<n / 1024, 256>>>(x);
    }

    // 2) fused dequant GEMM
    cudaFuncSetAttribute(quantlinear_kernel,
                         cudaFuncAttributeMaxDynamicSharedMemorySize, SMEM_BYTES);
    dim3 grid(N_DIM / BN, M / BM);       // (86, 32)
    quantlinear_kernel<<<grid, THREADS, SMEM_BYTES>>>(packed, scales, bias, out);
}